// round 14
// baseline (speedup 1.0000x reference)
#include <cuda_runtime.h>

// DotProcessorBlock: feat = x*w + b (per row, N=256)
// out[b, k] = feat[k>>8] * feat[k&255] for k in [0, 32896)
// B=4096 rows, ~539 MB of pure f32 stores -> HBM-write-bound (~91% of spec).
// R14: identical to the proven optimum (CHUNKS=16, BLOCK=256, barrier-free)
//      except stores use __stwt (write-through) instead of __stcs: probe
//      whether bypassing L2 dirty-line writeback scheduling smooths the
//      DRAM write stream. Only remaining untested cache operator.

#define N_FEAT 256
#define NUM_OUT 32896                 // N*(N+1)/2
#define OUT_VEC4 (NUM_OUT / 4)        // 8224 float4 per row
#define CHUNKS 16
#define CHUNK_V4 (OUT_VEC4 / CHUNKS)  // 514 float4 per chunk = 2*256 + 2

__global__ __launch_bounds__(256, 8)
void dot_outer_kernel(const float* __restrict__ x,
                      const float* __restrict__ w,
                      const float* __restrict__ bias,
                      float* __restrict__ out)
{
    const int row   = blockIdx.x >> 4;          // / CHUNKS
    const int chunk = blockIdx.x & (CHUNKS - 1);
    const int tid   = threadIdx.x;

    const int t0 = chunk * CHUNK_V4 + tid;
    const int j  = t0 & 63;                     // float4 column, invariant under t += 256
                                                // (tail +512: 512 % 64 == 0, still invariant)

    const float4* __restrict__ x4 = reinterpret_cast<const float4*>(x) + (size_t)row * (N_FEAT / 4);
    const float4* __restrict__ w4 = reinterpret_cast<const float4*>(w);
    const float4* __restrict__ b4 = reinterpret_cast<const float4*>(bias);

    // fj = feat[4j..4j+3] in registers (no smem, no barrier, warp-private latency)
    const float4 xa = x4[j];
    const float4 wa = w4[j];
    const float4 ba = b4[j];
    float4 fj;
    fj.x = fmaf(xa.x, wa.x, ba.x);
    fj.y = fmaf(xa.y, wa.y, ba.y);
    fj.z = fmaf(xa.z, wa.z, ba.z);
    fj.w = fmaf(xa.w, wa.w, ba.w);

    const float* __restrict__ xr = x + (size_t)row * N_FEAT;
    float4* __restrict__ out4 = reinterpret_cast<float4*>(out) + (size_t)row * OUT_VEC4;

    // Iteration 0 and 1 (always in range: CHUNK_V4 = 2*256 + 2)
    {
        const int i = t0 >> 6;                  // fi index, near-uniform per warp
        const float fi = fmaf(xr[i], w[i], bias[i]);
        float4 v = { fj.x * fi, fj.y * fi, fj.z * fi, fj.w * fi };
        __stwt(&out4[t0], v);
    }
    {
        const int t1 = t0 + 256;
        const int i = t1 >> 6;
        const float fi = fmaf(xr[i], w[i], bias[i]);
        float4 v = { fj.x * fi, fj.y * fi, fj.z * fi, fj.w * fi };
        __stwt(&out4[t1], v);
    }
    // 2-element tail (threads 0..1); fj index unchanged since 512 % 64 == 0
    if (tid < (CHUNK_V4 - 2 * 256)) {
        const int t2 = t0 + 512;
        const int i = t2 >> 6;
        const float fi = fmaf(xr[i], w[i], bias[i]);
        float4 v = { fj.x * fi, fj.y * fi, fj.z * fi, fj.w * fi };
        __stwt(&out4[t2], v);
    }
}

extern "C" void kernel_launch(void* const* d_in, const int* in_sizes, int n_in,
                              void* d_out, int out_size)
{
    const float* x    = (const float*)d_in[0];
    const float* w    = (const float*)d_in[1];
    const float* bias = (const float*)d_in[2];
    float* out        = (float*)d_out;

    const int B = in_sizes[0] / N_FEAT;   // 4096
    dot_outer_kernel<<<B * CHUNKS, 256>>>(x, w, bias, out);
}

// round 15
// speedup vs baseline: 1.3257x; 1.3257x over previous
#include <cuda_runtime.h>

// DotProcessorBlock: feat = x*w + b (per row, N=256)
// out[b, k] = feat[k>>8] * feat[k&255] for k in [0, 32896)
// B=4096 rows, ~539 MB of pure f32 stores -> HBM-write-bound.
//
// FINAL — measured 74.18us (x2) / 74.50us; ~7.27 TB/s = 91% of HBM spec.
// Full axis map from this session (timed-loop us):
//   cache op:  __stcs 74.2 | default 82.4 | __stwt 98.3
//   quantum:   CHUNKS=16 74.2 | 8 74.9 | 32 98.4
//   block:     256 74.2 | 128 119.5
//   prologue:  barrier-free 74.2 | smem+BAR 75.4 | front-batched loads 78.2
//   schedule:  per-launch 74.2 | persistent 94.4
//   alignment: 514-chunk 74.2 | 512-aligned 74.5 (neutral)
// Mechanism: pure HBM-write-bound; stores issue as soon as each store's own
// operands land; fine quantum minimizes end-of-kernel drain; streaming
// stores keep dead output lines from competing in L2.

#define N_FEAT 256
#define NUM_OUT 32896                 // N*(N+1)/2
#define OUT_VEC4 (NUM_OUT / 4)        // 8224 float4 per row
#define CHUNKS 16
#define CHUNK_V4 (OUT_VEC4 / CHUNKS)  // 514 float4 per chunk = 2*256 + 2

__global__ __launch_bounds__(256, 8)
void dot_outer_kernel(const float* __restrict__ x,
                      const float* __restrict__ w,
                      const float* __restrict__ bias,
                      float* __restrict__ out)
{
    const int row   = blockIdx.x >> 4;          // / CHUNKS
    const int chunk = blockIdx.x & (CHUNKS - 1);
    const int tid   = threadIdx.x;

    const int t0 = chunk * CHUNK_V4 + tid;
    const int j  = t0 & 63;                     // float4 column, invariant under t += 256
                                                // (tail +512: 512 % 64 == 0, still invariant)

    const float4* __restrict__ x4 = reinterpret_cast<const float4*>(x) + (size_t)row * (N_FEAT / 4);
    const float4* __restrict__ w4 = reinterpret_cast<const float4*>(w);
    const float4* __restrict__ b4 = reinterpret_cast<const float4*>(bias);

    // fj = feat[4j..4j+3] in registers (no smem, no barrier, warp-private latency)
    const float4 xa = x4[j];
    const float4 wa = w4[j];
    const float4 ba = b4[j];
    float4 fj;
    fj.x = fmaf(xa.x, wa.x, ba.x);
    fj.y = fmaf(xa.y, wa.y, ba.y);
    fj.z = fmaf(xa.z, wa.z, ba.z);
    fj.w = fmaf(xa.w, wa.w, ba.w);

    const float* __restrict__ xr = x + (size_t)row * N_FEAT;
    float4* __restrict__ out4 = reinterpret_cast<float4*>(out) + (size_t)row * OUT_VEC4;

    // Iteration 0 and 1 (always in range: CHUNK_V4 = 2*256 + 2)
    {
        const int i = t0 >> 6;                  // fi index, near-uniform per warp
        const float fi = fmaf(xr[i], w[i], bias[i]);
        float4 v = { fj.x * fi, fj.y * fi, fj.z * fi, fj.w * fi };
        __stcs(&out4[t0], v);
    }
    {
        const int t1 = t0 + 256;
        const int i = t1 >> 6;
        const float fi = fmaf(xr[i], w[i], bias[i]);
        float4 v = { fj.x * fi, fj.y * fi, fj.z * fi, fj.w * fi };
        __stcs(&out4[t1], v);
    }
    // 2-element tail (threads 0..1); fj index unchanged since 512 % 64 == 0
    if (tid < (CHUNK_V4 - 2 * 256)) {
        const int t2 = t0 + 512;
        const int i = t2 >> 6;
        const float fi = fmaf(xr[i], w[i], bias[i]);
        float4 v = { fj.x * fi, fj.y * fi, fj.z * fi, fj.w * fi };
        __stcs(&out4[t2], v);
    }
}

extern "C" void kernel_launch(void* const* d_in, const int* in_sizes, int n_in,
                              void* d_out, int out_size)
{
    const float* x    = (const float*)d_in[0];
    const float* w    = (const float*)d_in[1];
    const float* bias = (const float*)d_in[2];
    float* out        = (float*)d_out;

    const int B = in_sizes[0] / N_FEAT;   // 4096
    dot_outer_kernel<<<B * CHUNKS, 256>>>(x, w, bias, out);
}